// round 10
// baseline (speedup 1.0000x reference)
#include <cuda_runtime.h>
#include <cuda_bf16.h>

// CropAndResize: image [8,256,64,64] f32 NCHW, boxes [1000,4] f32 (y1,x1,y2,x2),
// box_ind [1000] i32. Output [1000,256,14,14] f32, TF-style bilinear,
// extrapolation_value = 0 for OOB sample coordinates.
//
// R8: NHWC strategy, float2 lanes, conflict-free swizzled result tile.
//  K1: transpose NCHW -> NHWC scratch (float4 writes), + zero page for OOB.
//  K2: warp = 64 consecutive channels (float2/lane); each tap one coalesced
//      LDG.64. Results staged in TWO [196][32] half-tiles at word index
//      p*32 + (col ^ (p&31)):
//        - STS (fixed p, col=lane): xor is a permutation -> conflict-free
//        - dump (fixed col, p consecutive): banks col^(p&31) -> conflict-free
//      Dump is then a straight coalesced NCHW copy.

namespace {
constexpr int C       = 256;
constexpr int H       = 64;
constexpr int W       = 64;
constexpr int HW      = H * W;           // 4096
constexpr int PLANE   = HW * C;          // per-batch elems (NHWC)
constexpr int CROP_W  = 14;
constexpr int PIX     = 196;
constexpr int CHG     = 64;              // channels per block
constexpr int NGRP    = C / CHG;         // 4
constexpr int BLOCK   = 512;             // 16 warps
constexpr int HTILE   = PIX * 32;        // 6272 words per half-tile
}

__device__ float g_imgT[8 * PLANE + 128];  // NHWC scratch + zero page

// ---------------- K1: NCHW -> NHWC transpose (float4 writes) + zero the pad
__global__ __launch_bounds__(256)
void transpose_kernel(const float* __restrict__ img)
{
    __shared__ float t[32][33];
    int b   = blockIdx.z;
    int tid = threadIdx.x;

    if (blockIdx.x == 0 && blockIdx.y == 0 && b == 0 && tid < 128)
        g_imgT[8 * PLANE + tid] = 0.0f;

    const float* src = img    + (long)b * PLANE;
    float*       dst = g_imgT + (long)b * PLANE;

    int x0 = blockIdx.x * 32;
    int c0 = blockIdx.y * 32;

    // read: coalesced along x, 32 channels
    int tx = tid & 31, ty = tid >> 5;    // ty 0..7
    #pragma unroll
    for (int j = 0; j < 4; ++j)
        t[ty + 8 * j][tx] = src[(long)(c0 + ty + 8 * j) * HW + x0 + tx];

    __syncthreads();

    // write: float4 along channel axis, coalesced
    int y = tid >> 3;                    // 0..31
    int g = tid & 7;                     // 0..7 (float4 group)
    float4 v;
    v.x = t[4 * g + 0][y];
    v.y = t[4 * g + 1][y];
    v.z = t[4 * g + 2][y];
    v.w = t[4 * g + 3][y];
    *(float4*)(dst + (long)(x0 + y) * C + c0 + 4 * g) = v;
}

// ---------------- K2: crop & resize from NHWC, float2 lanes, swizzled tile
__global__ __launch_bounds__(BLOCK, 4)
void crop_resize_kernel(const float4* __restrict__ boxes,
                        const int* __restrict__ box_ind,
                        float* __restrict__ out)
{
    extern __shared__ float smem[];
    float*  tileA = smem;                        // even channels [196][32]
    float*  tileB = smem + HTILE;                // odd channels
    int4*   s_off = (int4*)(smem + 2 * HTILE);   // [196] float2-unit offsets
    float2* s_xy  = (float2*)(s_off + PIX);      // [196] xl, yl

    int tid = threadIdx.x;
    int blk = blockIdx.x;                // box * NGRP + chgrp
    int box = blk >> 2;
    int c0  = (blk & 3) * CHG;

    float4 bb = boxes[box];              // y1, x1, y2, x2 (uniform)
    int    b  = __ldg(box_ind + box);

    if (tid < PIX) {
        float hs = ((bb.z - bb.x) * 63.0f) / 13.0f;
        float ws = ((bb.w - bb.y) * 63.0f) / 13.0f;
        float ybase = bb.x * 63.0f;
        float xbase = bb.y * 63.0f;

        int iy = tid / CROP_W;
        int ix = tid - iy * CROP_W;

        float in_y = ybase + (float)iy * hs;
        float in_x = xbase + (float)ix * ws;

        bool oob = (in_y < 0.0f) | (in_y > 63.0f) |
                   (in_x < 0.0f) | (in_x > 63.0f);

        float tf = floorf(in_y);
        float lf = floorf(in_x);
        float yl = in_y - tf;
        float xl = in_x - lf;

        int ti = min(max((int)tf, 0), 63);
        int bi = min(max((int)tf + 1, 0), 63);
        int li = min(max((int)lf, 0), 63);
        int ri = min(max((int)lf + 1, 0), 63);

        if (oob) {
            int zo = ((8 - b) * PLANE - c0) >> 1;      // -> zero page
            s_off[tid] = make_int4(zo, zo, zo, zo);
            s_xy[tid]  = make_float2(0.0f, 0.0f);
        } else {
            s_off[tid] = make_int4(((ti * W + li) * C) >> 1,
                                   ((ti * W + ri) * C) >> 1,
                                   ((bi * W + li) * C) >> 1,
                                   ((bi * W + ri) * C) >> 1);
            s_xy[tid]  = make_float2(xl, yl);
        }
    }
    __syncthreads();

    int lane  = tid & 31;                // 2 channels per lane
    int slice = tid >> 5;                // 16 pixel slices

    const float2* __restrict__ base =
        (const float2*)(g_imgT + (long)b * PLANE + c0) + lane;

    #pragma unroll 1
    for (int p = slice; p < PIX; p += 16) {
        int4   o = s_off[p];             // broadcast LDS (pre-shifted)
        float2 w = s_xy[p];

        float2 tl = __ldg(base + o.x);   // 64 consecutive ch per warp
        float2 tr = __ldg(base + o.y);
        float2 bl = __ldg(base + o.z);
        float2 br = __ldg(base + o.w);

        float vx, vy;
        {
            float top = tl.x + (tr.x - tl.x) * w.x;
            float bot = bl.x + (br.x - bl.x) * w.x;
            vx = top + (bot - top) * w.y;
        }
        {
            float top = tl.y + (tr.y - tl.y) * w.x;
            float bot = bl.y + (br.y - bl.y) * w.x;
            vy = top + (bot - top) * w.y;
        }

        int idx = (p << 5) + (lane ^ (p & 31));
        tileA[idx] = vx;                 // local channel 2*lane   (even)
        tileB[idx] = vy;                 // local channel 2*lane+1 (odd)
    }
    __syncthreads();

    // dump: out[(box*256 + c0 + c)*196 + p] = tile[(c&1)][p][c>>1], coalesced
    float* __restrict__ dst = out + ((long)box * C + c0) * PIX;
    int c = tid / PIX;                   // 0..2 for tid < 512
    int p = tid - c * PIX;
    #pragma unroll 1
    for (int i = tid; i < CHG * PIX; i += BLOCK) {
        const float* tt = smem + (c & 1) * HTILE;
        dst[i] = tt[(p << 5) + ((c >> 1) ^ (p & 31))];
        p += 120; c += 2;                // advance by 512 = 2*196 + 120
        if (p >= PIX) { p -= PIX; c += 1; }
    }
}

extern "C" void kernel_launch(void* const* d_in, const int* in_sizes, int n_in,
                              void* d_out, int out_size)
{
    const float*  img     = (const float*)d_in[0];
    const float4* boxes   = (const float4*)d_in[1];
    const int*    box_ind = (const int*)d_in[2];
    float*        out     = (float*)d_out;

    int n_boxes = in_sizes[2];                        // 1000

    dim3 tgrid(HW / 32, C / 32, 8);
    transpose_kernel<<<tgrid, 256>>>(img);

    size_t shmem = (size_t)(2 * HTILE) * 4 + (size_t)PIX * (16 + 8); // 54880 B
    cudaFuncSetAttribute(crop_resize_kernel,
                         cudaFuncAttributeMaxDynamicSharedMemorySize, (int)shmem);

    int blocks = n_boxes * NGRP;                      // 4000
    crop_resize_kernel<<<blocks, BLOCK, shmem>>>(boxes, box_ind, out);
}

// round 11
// speedup vs baseline: 1.0439x; 1.0439x over previous
#include <cuda_runtime.h>
#include <cuda_bf16.h>

// CropAndResize: image [8,256,64,64] f32 NCHW, boxes [1000,4] f32 (y1,x1,y2,x2),
// box_ind [1000] i32. Output [1000,256,14,14] f32, TF-style bilinear,
// extrapolation_value = 0 for OOB sample coordinates.
//
// R9: NHWC, float4 lanes (128 channels/warp/tap via LDG.128), two pixel
// phases (128 + 68) through a reused [128][66] x2 half-tile, and a fully
// regular dump: each warp owns (pixel-block, channel-residue), iterates 32
// channels with constant LDS/STG increments -> unrolled [R+imm] addressing.

namespace {
constexpr int C       = 256;
constexpr int H       = 64;
constexpr int W       = 64;
constexpr int HW      = H * W;           // 4096
constexpr int PLANE   = HW * C;          // per-batch elems (NHWC)
constexpr int CROP_W  = 14;
constexpr int PIX     = 196;
constexpr int CHG     = 128;             // channels per block
constexpr int NGRP    = C / CHG;         // 2
constexpr int BLOCK   = 512;             // 16 warps
constexpr int PITCH   = 66;              // tile row pitch (words)
constexpr int TROWS   = 128;             // tile rows (phase A size)
constexpr int HT      = TROWS * PITCH;   // 8448 words per half-tile
}

__device__ __align__(16) float g_imgT[8 * PLANE + 128];  // NHWC scratch + zero page

// ---------------- K1: NCHW -> NHWC transpose (float4 writes) + zero the pad
__global__ __launch_bounds__(256)
void transpose_kernel(const float* __restrict__ img)
{
    __shared__ float t[32][33];
    int b   = blockIdx.z;
    int tid = threadIdx.x;

    if (blockIdx.x == 0 && blockIdx.y == 0 && b == 0 && tid < 128)
        g_imgT[8 * PLANE + tid] = 0.0f;

    const float* src = img    + (long)b * PLANE;
    float*       dst = g_imgT + (long)b * PLANE;

    int x0 = blockIdx.x * 32;
    int c0 = blockIdx.y * 32;

    int tx = tid & 31, ty = tid >> 5;    // ty 0..7
    #pragma unroll
    for (int j = 0; j < 4; ++j)
        t[ty + 8 * j][tx] = src[(long)(c0 + ty + 8 * j) * HW + x0 + tx];

    __syncthreads();

    int y = tid >> 3;                    // 0..31
    int g = tid & 7;                     // 0..7 (float4 group)
    float4 v;
    v.x = t[4 * g + 0][y];
    v.y = t[4 * g + 1][y];
    v.z = t[4 * g + 2][y];
    v.w = t[4 * g + 3][y];
    *(float4*)(dst + (long)(x0 + y) * C + c0 + 4 * g) = v;
}

// ---------------- K2: crop & resize from NHWC, float4 lanes, 2 pixel phases
__global__ __launch_bounds__(BLOCK, 3)
void crop_resize_kernel(const float4* __restrict__ boxes,
                        const int* __restrict__ box_ind,
                        float* __restrict__ out)
{
    extern __shared__ float smem[];
    // [0, HT)        : half-tile E (lane channels 4l, 4l+1)
    // [HT, 2*HT)     : half-tile O (lane channels 4l+2, 4l+3)
    int4*   s_off = (int4*)(smem + 2 * HT);      // [196] float4-unit tap offsets
    float2* s_xy  = (float2*)(s_off + PIX);      // [196] xl, yl

    int tid = threadIdx.x;
    int blk = blockIdx.x;                // box * NGRP + chgrp
    int box = blk >> 1;
    int c0  = (blk & 1) * CHG;

    float4 bb = boxes[box];              // y1, x1, y2, x2 (uniform)
    int    b  = __ldg(box_ind + box);

    if (tid < PIX) {
        float hs = ((bb.z - bb.x) * 63.0f) / 13.0f;
        float ws = ((bb.w - bb.y) * 63.0f) / 13.0f;
        float ybase = bb.x * 63.0f;
        float xbase = bb.y * 63.0f;

        int iy = tid / CROP_W;
        int ix = tid - iy * CROP_W;

        float in_y = ybase + (float)iy * hs;
        float in_x = xbase + (float)ix * ws;

        bool oob = (in_y < 0.0f) | (in_y > 63.0f) |
                   (in_x < 0.0f) | (in_x > 63.0f);

        float tf = floorf(in_y);
        float lf = floorf(in_x);
        float yl = in_y - tf;
        float xl = in_x - lf;

        int ti = min(max((int)tf, 0), 63);
        int bi = min(max((int)tf + 1, 0), 63);
        int li = min(max((int)lf, 0), 63);
        int ri = min(max((int)lf + 1, 0), 63);

        if (oob) {
            int zo = ((8 - b) * PLANE - c0) >> 2;      // -> zero page (f4 units)
            s_off[tid] = make_int4(zo, zo, zo, zo);
            s_xy[tid]  = make_float2(0.0f, 0.0f);
        } else {
            s_off[tid] = make_int4((ti * W + li) << 6,  // *C/4 = *64
                                   (ti * W + ri) << 6,
                                   (bi * W + li) << 6,
                                   (bi * W + ri) << 6);
            s_xy[tid]  = make_float2(xl, yl);
        }
    }
    __syncthreads();

    int lane  = tid & 31;                // 4 channels per lane
    int slice = tid >> 5;                // 16 pixel slices

    const float4* __restrict__ base =
        (const float4*)(g_imgT + (long)b * PLANE + c0) + lane;

    // dump decomposition: warp -> fixed pixel-block + channel residue
    int wrp  = tid >> 5;
    int pblk = wrp & 3;                  // pixel block of 32
    int w4   = wrp >> 2;                 // channel residue 0..3
    int tsel = (w4 >> 1) & 1;
    int prow = pblk * 32 + lane;         // tile row this lane dumps
    const float* tb = smem + tsel * HT + prow * PITCH + (w4 & 1);
    float* dst0 = out + ((long)box * C + c0 + w4) * PIX;

    #pragma unroll 1
    for (int phase = 0; phase < 2; ++phase) {
        int p0 = phase * TROWS;          // 0 or 128
        int pe = phase ? PIX : TROWS;    // 128 or 196

        // ---- mainloop: bilinear taps, 128 channels per warp per pixel ----
        #pragma unroll 1
        for (int p = p0 + slice; p < pe; p += 16) {
            int4   o = s_off[p];         // broadcast LDS (float4 units)
            float2 w = s_xy[p];

            float4 tl = __ldg(base + o.x);   // 512B coalesced per warp
            float4 tr = __ldg(base + o.y);
            float4 bl = __ldg(base + o.z);
            float4 br = __ldg(base + o.w);

            float v0, v1, v2, v3;
            { float t = tl.x + (tr.x - tl.x) * w.x;
              float u = bl.x + (br.x - bl.x) * w.x;
              v0 = t + (u - t) * w.y; }
            { float t = tl.y + (tr.y - tl.y) * w.x;
              float u = bl.y + (br.y - bl.y) * w.x;
              v1 = t + (u - t) * w.y; }
            { float t = tl.z + (tr.z - tl.z) * w.x;
              float u = bl.z + (br.z - bl.z) * w.x;
              v2 = t + (u - t) * w.y; }
            { float t = tl.w + (tr.w - tl.w) * w.x;
              float u = bl.w + (br.w - bl.w) * w.x;
              v3 = t + (u - t) * w.y; }

            int pr = p - p0;
            *(float2*)(smem +      pr * PITCH + 2 * lane) = make_float2(v0, v1);
            *(float2*)(smem + HT + pr * PITCH + 2 * lane) = make_float2(v2, v3);
        }
        __syncthreads();

        // ---- dump: warp-regular, constant increments, unrolled ----
        int p = p0 + prow;
        if (p < PIX) {
            float* dst = dst0 + p;
            #pragma unroll 8
            for (int it = 0; it < 32; ++it)
                dst[it * 4 * PIX] = tb[2 * it];   // channel c = 4*it + w4
        }
        __syncthreads();
    }
}

extern "C" void kernel_launch(void* const* d_in, const int* in_sizes, int n_in,
                              void* d_out, int out_size)
{
    const float*  img     = (const float*)d_in[0];
    const float4* boxes   = (const float4*)d_in[1];
    const int*    box_ind = (const int*)d_in[2];
    float*        out     = (float*)d_out;

    int n_boxes = in_sizes[2];                        // 1000

    dim3 tgrid(HW / 32, C / 32, 8);
    transpose_kernel<<<tgrid, 256>>>(img);

    size_t shmem = (size_t)(2 * HT) * 4 + (size_t)PIX * (16 + 8);  // 72288 B
    cudaFuncSetAttribute(crop_resize_kernel,
                         cudaFuncAttributeMaxDynamicSharedMemorySize, (int)shmem);

    int blocks = n_boxes * NGRP;                      // 2000
    crop_resize_kernel<<<blocks, BLOCK, shmem>>>(boxes, box_ind, out);
}